// round 9
// baseline (speedup 1.0000x reference)
#include <cuda_runtime.h>
#include <cstdint>

#define NV_P   32
#define C_VX   0.16f
#define C_VY   0.16f
#define C_VZ   4.0f
#define C_XOFF 0.08f
#define C_YOFF -39.6f
#define C_ZOFF -1.0f
#define BN_EPS 1e-3f

#define K1_BLOCKS 296
#define K1_THREADS 256
#define K3_BLOCKS 592
#define K3_THREADS 256
#define NSTAT 70   // 10 mean (natural) + 60 = 30 packed-S pairs

// -------- global scratch (allocation-free rule: __device__ globals) --------
__device__ float  g_part[NSTAT * K1_BLOCKS];   // transposed: [stat][block] for coalesced kred
__device__ double g_stat[NSTAT];
__device__ float  g_ab[128];                   // |a|[0..63], b[64..127]
__device__ float4 g_mc4[131072];               // per-voxel (mx,my,mz,cx)
__device__ float2 g_c2[131072];                // per-voxel (cy,cz)

// ---------------- packed f32x2 helpers ----------------
__device__ __forceinline__ unsigned long long pk2(float lo, float hi) {
    unsigned long long r;
    asm("mov.b64 %0, {%1, %2};" : "=l"(r) : "f"(lo), "f"(hi));
    return r;
}
__device__ __forceinline__ void unpk2(unsigned long long x, float& lo, float& hi) {
    asm("mov.b64 {%0, %1}, %2;" : "=f"(lo), "=f"(hi) : "l"(x));
}
__device__ __forceinline__ unsigned long long fma2(unsigned long long a, unsigned long long b, unsigned long long c) {
    unsigned long long d;
    asm("fma.rn.f32x2 %0, %1, %2, %3;" : "=l"(d) : "l"(a), "l"(b), "l"(c));
    return d;
}
__device__ __forceinline__ unsigned long long add2(unsigned long long a, unsigned long long b) {
    unsigned long long d;
    asm("add.rn.f32x2 %0, %1, %2;" : "=l"(d) : "l"(a), "l"(b));
    return d;
}
__device__ __forceinline__ unsigned long long mul2(unsigned long long a, unsigned long long b) {
    unsigned long long d;
    asm("mul.rn.f32x2 %0, %1, %2;" : "=l"(d) : "l"(a), "l"(b));
    return d;
}
// two interleaved 3-way butterfly sums (independent chains overlap their SHFL latency)
__device__ __forceinline__ void wred6(float& a, float& b, float& c,
                                      float& d, float& e, float& f) {
#pragma unroll
    for (int off = 16; off; off >>= 1) {
        a += __shfl_xor_sync(0xffffffffu, a, off);
        d += __shfl_xor_sync(0xffffffffu, d, off);
        b += __shfl_xor_sync(0xffffffffu, b, off);
        e += __shfl_xor_sync(0xffffffffu, e, off);
        c += __shfl_xor_sync(0xffffffffu, c, off);
        f += __shfl_xor_sync(0xffffffffu, f, off);
    }
}

// ---------------- k1: packed feature moments, 2 voxels in flight per warp ----------------
__global__ __launch_bounds__(K1_THREADS, 2) void k1_stats(
    const float* __restrict__ vf, const int* __restrict__ vnp,
    const int* __restrict__ coords, int V)
{
    unsigned long long SP[30];     // packed S: i in 0..9, j2 in i/2..4 -> (f_i*f_{2j2}, f_i*f_{2j2+1})
    unsigned long long mp[5];      // packed m: (f0,f1),(f2,f3),(f4,f5),(f6,f7),(f8,f9)
#pragma unroll
    for (int i = 0; i < 30; i++) SP[i] = 0ull;
#pragma unroll
    for (int i = 0; i < 5; i++) mp[i] = 0ull;

    const int lane = threadIdx.x & 31;
    const int wib  = threadIdx.x >> 5;
    const int gw   = (blockIdx.x * blockDim.x + threadIdx.x) >> 5;
    const int nw   = (gridDim.x * blockDim.x) >> 5;

    // two voxels in flight: va, vb = va+nw; stride 2*nw; prefetch next pair (pt only)
    int va = gw, vb = gw + nw;
    float4 ptA, ptB;
    if (va < V) ptA = reinterpret_cast<const float4*>(vf)[va * NV_P + lane];
    if (vb < V) ptB = reinterpret_cast<const float4*>(vf)[vb * NV_P + lane];

    while (va < V) {
        int va2 = va + 2 * nw, vb2 = vb + 2 * nw;
        float4 ptA2, ptB2;
        if (va2 < V) ptA2 = reinterpret_cast<const float4*>(vf)[va2 * NV_P + lane];
        if (vb2 < V) ptB2 = reinterpret_cast<const float4*>(vf)[vb2 * NV_P + lane];

        const bool hasB = vb < V;
        int  cntA = vnp[va];
        int4 cA   = reinterpret_cast<const int4*>(coords)[va];
        int  cntB = 1;  int4 cB = make_int4(0, 0, 0, 0);
        if (hasB) {
            cntB = vnp[vb];
            cB   = reinterpret_cast<const int4*>(coords)[vb];
        }

        // interleaved warp sums for both voxels (sum over ALL 32 points, matches ref)
        float sxA = ptA.x, syA = ptA.y, szA = ptA.z;
        float sxB = hasB ? ptB.x : 0.f, syB = hasB ? ptB.y : 0.f, szB = hasB ? ptB.z : 0.f;
        wred6(sxA, syA, szA, sxB, syB, szB);

        float invA = 1.0f / (float)cntA;
        float mxA = sxA * invA, myA = syA * invA, mzA = szA * invA;
        float cxA = (float)cA.w * C_VX + C_XOFF;
        float cyA = (float)cA.z * C_VY + C_YOFF;
        float czA = (float)cA.y * C_VZ + C_ZOFF;
        float invB = 1.0f / (float)cntB;
        float mxB = sxB * invB, myB = syB * invB, mzB = szB * invB;
        float cxB = (float)cB.w * C_VX + C_XOFF;
        float cyB = (float)cB.z * C_VY + C_YOFF;
        float czB = (float)cB.y * C_VZ + C_ZOFF;
        if (lane == 0) {
            g_mc4[va] = make_float4(mxA, myA, mzA, cxA);
            g_c2[va]  = make_float2(cyA, czA);
            if (hasB) {
                g_mc4[vb] = make_float4(mxB, myB, mzB, cxB);
                g_c2[vb]  = make_float2(cyB, czB);
            }
        }

        // ---- stats body voxel A ----
        if (lane < cntA) {
            unsigned long long g[5];
            g[0] = pk2(ptA.x, ptA.y); g[1] = pk2(ptA.z, ptA.w);
            g[2] = pk2(ptA.x - mxA, ptA.y - myA);
            g[3] = pk2(ptA.z - mzA, ptA.x - cxA);
            g[4] = pk2(ptA.y - cyA, ptA.z - czA);
#pragma unroll
            for (int k = 0; k < 5; k++) mp[k] = add2(mp[k], g[k]);
            float fs[10] = {ptA.x, ptA.y, ptA.z, ptA.w,
                            ptA.x - mxA, ptA.y - myA, ptA.z - mzA,
                            ptA.x - cxA, ptA.y - cyA, ptA.z - czA};
            int idx = 0;
#pragma unroll
            for (int i = 0; i < 10; i++) {
                unsigned long long bi = pk2(fs[i], fs[i]);
#pragma unroll
                for (int j2 = i / 2; j2 < 5; j2++) { SP[idx] = fma2(bi, g[j2], SP[idx]); idx++; }
            }
        }
        // ---- stats body voxel B ----
        if (hasB && lane < cntB) {
            unsigned long long g[5];
            g[0] = pk2(ptB.x, ptB.y); g[1] = pk2(ptB.z, ptB.w);
            g[2] = pk2(ptB.x - mxB, ptB.y - myB);
            g[3] = pk2(ptB.z - mzB, ptB.x - cxB);
            g[4] = pk2(ptB.y - cyB, ptB.z - czB);
#pragma unroll
            for (int k = 0; k < 5; k++) mp[k] = add2(mp[k], g[k]);
            float fs[10] = {ptB.x, ptB.y, ptB.z, ptB.w,
                            ptB.x - mxB, ptB.y - myB, ptB.z - mzB,
                            ptB.x - cxB, ptB.y - cyB, ptB.z - czB};
            int idx = 0;
#pragma unroll
            for (int i = 0; i < 10; i++) {
                unsigned long long bi = pk2(fs[i], fs[i]);
#pragma unroll
                for (int j2 = i / 2; j2 < 5; j2++) { SP[idx] = fma2(bi, g[j2], SP[idx]); idx++; }
            }
        }

        va = va2; vb = vb2; ptA = ptA2; ptB = ptB2;
    }

    // warp butterfly on packed accumulators (64-bit shfl) — tail only
#pragma unroll
    for (int k = 0; k < 5; k++)
#pragma unroll
        for (int off = 16; off; off >>= 1)
            mp[k] = add2(mp[k], __shfl_xor_sync(0xffffffffu, mp[k], off));
#pragma unroll
    for (int n = 0; n < 30; n++)
#pragma unroll
        for (int off = 16; off; off >>= 1)
            SP[n] = add2(SP[n], __shfl_xor_sync(0xffffffffu, SP[n], off));

    __shared__ float red[8 * NSTAT];
    if (lane == 0) {
#pragma unroll
        for (int k = 0; k < 5; k++) {
            float lo, hi; unpk2(mp[k], lo, hi);
            red[wib * NSTAT + 2 * k] = lo; red[wib * NSTAT + 2 * k + 1] = hi;
        }
#pragma unroll
        for (int n = 0; n < 30; n++) {
            float lo, hi; unpk2(SP[n], lo, hi);
            red[wib * NSTAT + 10 + 2 * n] = lo; red[wib * NSTAT + 10 + 2 * n + 1] = hi;
        }
    }
    __syncthreads();
    int t = threadIdx.x;
    if (t < NSTAT) {
        float s = 0.f;
#pragma unroll
        for (int w = 0; w < 8; w++) s += red[w * NSTAT + t];
        g_part[t * K1_BLOCKS + blockIdx.x] = s;    // transposed for coalesced kred
    }
}

// ---------------- kred: reduce per-block partials in double ----------------
__global__ void kred_stats() {
    int b = blockIdx.x;
    double s = 0.0;
    for (int i = threadIdx.x; i < K1_BLOCKS; i += blockDim.x)
        s += (double)g_part[b * K1_BLOCKS + i];
    __shared__ double sd[256];
    sd[threadIdx.x] = s;
    __syncthreads();
    for (int off = 128; off; off >>= 1) {
        if (threadIdx.x < off) sd[threadIdx.x] += sd[threadIdx.x + off];
        __syncthreads();
    }
    if (threadIdx.x == 0) g_stat[b] = sd[0];
}

// ---------------- k2: fold BN into |a|, b (dup-aware packed-S coefficients) ----------------
__global__ void k2_coef(const float* __restrict__ W, const float* __restrict__ gamma,
                        const float* __restrict__ beta, double invN)
{
    int o = threadIdx.x;
    if (o >= 64) return;
    double w[10];
#pragma unroll
    for (int c = 0; c < 10; c++) w[c] = (double)W[o * 10 + c];
    double mean = 0.0;
#pragma unroll
    for (int c = 0; c < 10; c++) mean += w[c] * g_stat[c];
    mean *= invN;
    double e2 = 0.0;
    int idx = 0;
#pragma unroll
    for (int i = 0; i < 10; i++) {
#pragma unroll
        for (int j2 = i / 2; j2 < 5; j2++) {
#pragma unroll
            for (int lsel = 0; lsel < 2; lsel++) {
                int j = 2 * j2 + lsel;
                double Sv = g_stat[10 + idx * 2 + lsel];
                // {2k,2k+1} pairs appear twice in packed set -> coef 1; diag 1; else 2
                double coef = (j == i) ? 1.0 : (((i ^ j) == 1) ? 1.0 : 2.0);
                e2 += coef * w[i] * w[j] * Sv;
            }
            idx++;
        }
    }
    e2 *= invN;
    double var = e2 - mean * mean;
    float a = gamma[o] * rsqrtf((float)var + BN_EPS);
    float b = beta[o] - (float)mean * a;
    g_ab[o]      = fabsf(a);                 // k3 folds sign(a)=sign(gamma) itself
    g_ab[64 + o] = b;
}

// ---------------- k3: point-pair packed max of s*(u.p); final affine+relu output ----------------
__global__ __launch_bounds__(K3_THREADS, 4) void k3_out(
    const float* __restrict__ vf, const int* __restrict__ vnp,
    const float* __restrict__ W, const float* __restrict__ gamma,
    float* __restrict__ out, int V)
{
    __shared__ __align__(16) float sh[8 * NV_P * 4];   // 8 warps * 16 pairs * 32B = 4KB staging
    const int lane = threadIdx.x & 31;
    const int wib  = threadIdx.x >> 5;
    const int gw   = (blockIdx.x * blockDim.x + threadIdx.x) >> 5;
    const int nw   = (gridDim.x * blockDim.x) >> 5;
    float* msh = sh + wib * (NV_P * 4);

    // lane owns output channels A=2*lane, B=2*lane+1; sign(a)=sign(gamma)
    const float* wA = W + (2 * lane) * 10;
    const float* wB = wA + 10;
    float sA = (gamma[2 * lane]     >= 0.f) ? 1.f : -1.f;
    float sB = (gamma[2 * lane + 1] >= 0.f) ? 1.f : -1.f;
    float uA0s = sA * (wA[0] + wA[4] + wA[7]);
    float uA1s = sA * (wA[1] + wA[5] + wA[8]);
    float uA2s = sA * (wA[2] + wA[6] + wA[9]);
    float uA3s = sA * wA[3];
    float uB0s = sB * (wB[0] + wB[4] + wB[7]);
    float uB1s = sB * (wB[1] + wB[5] + wB[8]);
    float uB2s = sB * (wB[2] + wB[6] + wB[9]);
    float uB3s = sB * wB[3];
    unsigned long long uA0 = pk2(uA0s, uA0s), uA1 = pk2(uA1s, uA1s);
    unsigned long long uA2 = pk2(uA2s, uA2s), uA3 = pk2(uA3s, uA3s);
    unsigned long long uB0 = pk2(uB0s, uB0s), uB1 = pk2(uB1s, uB1s);
    unsigned long long uB2 = pk2(uB2s, uB2s), uB3 = pk2(uB3s, uB3s);

    float2 av = reinterpret_cast<const float2*>(g_ab)[lane];        // |a| pair
    float2 bv = reinterpret_cast<const float2*>(g_ab + 64)[lane];   // b pair

    // depth-1 prefetch of the big load only (pt) + cnt
    int v = gw;
    float4 pt; int cnt;
    if (v < V) {
        pt  = reinterpret_cast<const float4*>(vf)[v * NV_P + lane];
        cnt = vnp[v];
    }
    while (v < V) {
        int vn = v + nw;
        float4 ptn; int cntn;
        if (vn < V) {
            ptn  = reinterpret_cast<const float4*>(vf)[vn * NV_P + lane];
            cntn = vnp[vn];
        }
        // per-voxel mean/center: small, L2-hot, consumed ~200cyc later at base
        float4 mc = g_mc4[v];
        float2 c2 = g_c2[v];
        // base weights from W (L1-resident): consumed at base only
        float2 w4 = make_float2(wA[4], wB[4]);
        float2 w5 = make_float2(wA[5], wB[5]);
        float2 w6 = make_float2(wA[6], wB[6]);
        float2 w7 = make_float2(wA[7], wB[7]);
        float2 w8 = make_float2(wA[8], wB[8]);
        float2 w9 = make_float2(wA[9], wB[9]);

        // stage pair-transposed point data: pair k at byte offset 32k:
        //   [x0,x1,y0,y1],[z0,z1,w0,w1] ; lane writes 16B at msh+16*lane
        __syncwarp();
        {
            float px = __shfl_xor_sync(0xffffffffu, pt.x, 1);
            float py = __shfl_xor_sync(0xffffffffu, pt.y, 1);
            float pz = __shfl_xor_sync(0xffffffffu, pt.z, 1);
            float pw = __shfl_xor_sync(0xffffffffu, pt.w, 1);
            float4 st;
            if (lane & 1) st = make_float4(pz, pt.z, pw, pt.w);
            else          st = make_float4(pt.x, px, pt.y, py);
            reinterpret_cast<float4*>(msh)[lane] = st;
        }
        __syncwarp();

        // max over points of s*(u . p), two points per iteration
        float mA = -3.402823466e38f, mB = -3.402823466e38f;
        const ulonglong2* pp = reinterpret_cast<const ulonglong2*>(msh);
        int npair = cnt >> 1;
        for (int k = 0; k < npair; k++) {
            ulonglong2 q = pp[2 * k];       // (x0,x1),(y0,y1)
            ulonglong2 r = pp[2 * k + 1];   // (z0,z1),(w0,w1)
            unsigned long long aA = mul2(q.x, uA0);
            unsigned long long aB = mul2(q.x, uB0);
            aA = fma2(q.y, uA1, aA);  aB = fma2(q.y, uB1, aB);
            aA = fma2(r.x, uA2, aA);  aB = fma2(r.x, uB2, aB);
            aA = fma2(r.y, uA3, aA);  aB = fma2(r.y, uB3, aB);
            float t0, t1;
            unpk2(aA, t0, t1); mA = fmaxf(mA, fmaxf(t0, t1));
            unpk2(aB, t0, t1); mB = fmaxf(mB, fmaxf(t0, t1));
        }
        if (cnt & 1) {   // odd count: low half of last pair only
            ulonglong2 q = pp[2 * npair];
            ulonglong2 r = pp[2 * npair + 1];
            unsigned long long aA = mul2(q.x, uA0);
            unsigned long long aB = mul2(q.x, uB0);
            aA = fma2(q.y, uA1, aA);  aB = fma2(q.y, uB1, aB);
            aA = fma2(r.x, uA2, aA);  aB = fma2(r.x, uB2, aB);
            aA = fma2(r.y, uA3, aA);  aB = fma2(r.y, uB3, aB);
            float t0, t1;
            unpk2(aA, t0, t1); mA = fmaxf(mA, t0);
            unpk2(aB, t0, t1); mB = fmaxf(mB, t0);
        }

        // base = s * ( -(mean . w[4:7]) - (center . w[7:10]) )
        float baA = -(mc.x * w4.x + mc.y * w5.x + mc.z * w6.x + mc.w * w7.x + c2.x * w8.x + c2.y * w9.x);
        float baB = -(mc.x * w4.y + mc.y * w5.y + mc.z * w6.y + mc.w * w7.y + c2.x * w8.y + c2.y * w9.y);
        float xA = mA + sA * baA;
        float xB = mB + sB * baB;
        if (cnt < NV_P) { xA = fmaxf(xA, 0.f); xB = fmaxf(xB, 0.f); }  // masked rows: raw x = 0
        float r0o = fmaxf(fmaf(av.x, xA, bv.x), 0.f);
        float r1o = fmaxf(fmaf(av.y, xB, bv.y), 0.f);
        reinterpret_cast<float2*>(out)[v * 32 + lane] = make_float2(r0o, r1o);

        v = vn; pt = ptn; cnt = cntn;
    }
}

extern "C" void kernel_launch(void* const* d_in, const int* in_sizes, int n_in,
                              void* d_out, int out_size) {
    const float* vf     = (const float*)d_in[0];
    const int*   vnp    = (const int*)d_in[1];
    const int*   coords = (const int*)d_in[2];
    const float* W      = (const float*)d_in[3];
    const float* gamma  = (const float*)d_in[4];
    const float* beta   = (const float*)d_in[5];
    float* out = (float*)d_out;
    int V = in_sizes[1];   // voxel_num_points element count

    k1_stats<<<K1_BLOCKS, K1_THREADS>>>(vf, vnp, coords, V);
    kred_stats<<<NSTAT, 256>>>();
    double invN = 1.0 / ((double)V * (double)NV_P);
    k2_coef<<<1, 64>>>(W, gamma, beta, invN);
    k3_out<<<K3_BLOCKS, K3_THREADS>>>(vf, vnp, W, gamma, out, V);
}